// round 1
// baseline (speedup 1.0000x reference)
#include <cuda_runtime.h>
#include <math.h>

// ---------------- static config ----------------
#define BB      16
#define HH      64
#define WW      64
#define CC      512
#define HEADS   16
#define WSZ     8
#define SHIFT   4
#define NTOK    64          // tokens per window
#define NWIN    64          // windows per image
#define HID     2048
#define HD      32          // head dim
#define MTOK    (BB*HH*WW)  // 65536 rows
#define SCALE_F 0.17677669529663687f
#define EPSF    1e-5f

// ---------------- scratch (static device memory; no allocs) ----------------
__device__ float g_hwin[(size_t)MTOK * CC];        // LN1 + shift + window partition
__device__ float g_qkv [(size_t)MTOK * 3 * CC];    // qkv projection
__device__ float g_o   [(size_t)MTOK * CC];        // attention output (win layout)
__device__ float g_x1  [(size_t)MTOK * CC];        // residual 1
__device__ float g_h2n [(size_t)MTOK * CC];        // LN2 output
__device__ float g_hid [(size_t)MTOK * HID];       // MLP hidden

// ---------------- LayerNorm (+ optional shift/window-partition gather) -----
template<bool SHIFTED>
__global__ void ln_kernel(const float* __restrict__ x,
                          const float* __restrict__ w,
                          const float* __restrict__ b,
                          float* __restrict__ out)
{
    __shared__ float sh[4];
    int m   = blockIdx.x;          // output row (window layout if SHIFTED)
    int tid = threadIdx.x;         // 128 threads, 4 floats each

    size_t dst_row = (size_t)m * CC;
    size_t src_row;
    if (SHIFTED) {
        int bb  = m >> 12;
        int rem = m & 4095;
        int wdx = rem >> 6, n = rem & 63;
        int wh = wdx >> 3, ww = wdx & 7;
        int r  = n   >> 3, s  = n   & 7;
        int shp = ((wh << 3) + r + SHIFT) & 63;
        int swp = ((ww << 3) + s + SHIFT) & 63;
        src_row = ((size_t)bb * 4096 + shp * 64 + swp) * CC;
    } else {
        src_row = dst_row;
    }

    float4 v = ((const float4*)(x + src_row))[tid];

    // --- reduce sum ---
    float sum = v.x + v.y + v.z + v.w;
    #pragma unroll
    for (int o = 16; o > 0; o >>= 1) sum += __shfl_xor_sync(0xffffffffu, sum, o);
    if ((tid & 31) == 0) sh[tid >> 5] = sum;
    __syncthreads();
    float mean = (sh[0] + sh[1] + sh[2] + sh[3]) * (1.0f / CC);
    __syncthreads();

    // --- reduce variance ---
    float d0 = v.x - mean, d1 = v.y - mean, d2 = v.z - mean, d3 = v.w - mean;
    float sq = d0*d0 + d1*d1 + d2*d2 + d3*d3;
    #pragma unroll
    for (int o = 16; o > 0; o >>= 1) sq += __shfl_xor_sync(0xffffffffu, sq, o);
    if ((tid & 31) == 0) sh[tid >> 5] = sq;
    __syncthreads();
    float var = (sh[0] + sh[1] + sh[2] + sh[3]) * (1.0f / CC);
    float inv = rsqrtf(var + EPSF);

    float4 w4 = ((const float4*)w)[tid];
    float4 b4 = ((const float4*)b)[tid];
    float4 o4;
    o4.x = d0 * inv * w4.x + b4.x;
    o4.y = d1 * inv * w4.y + b4.y;
    o4.z = d2 * inv * w4.z + b4.z;
    o4.w = d3 * inv * w4.w + b4.w;
    ((float4*)(out + dst_row))[tid] = o4;
}

// ---------------- generic tiled GEMM:  C[M,N] = A[M,K] @ Bw[N,K]^T ---------
// Epilogues:
#define EPI_PLAIN       0   // + bias
#define EPI_GELU        1   // + bias, exact GELU
#define EPI_SCATTER_RES 2   // + bias, window-reverse + roll + residual(x)
#define EPI_RES         3   // + bias, residual add (same layout)

template<int EPI>
__global__ void gemm64(const float* __restrict__ A,
                       const float* __restrict__ Bw,
                       const float* __restrict__ bias,
                       float* __restrict__ Cout,
                       int M, int Nc, int K,
                       const float* __restrict__ Res)
{
    __shared__ float sA[16][68];
    __shared__ float sB[16][68];

    int bm  = blockIdx.y * 64;
    int bn  = blockIdx.x * 64;
    int tid = threadIdx.x;          // 256
    int ty  = tid >> 4, tx = tid & 15;

    float acc[4][4] = {};

    int lr  = tid >> 2;             // 0..63 tile row
    int lk4 = (tid & 3) * 4;        // k sub-offset
    const float* Arow = A  + (size_t)(bm + lr) * K + lk4;
    const float* Brow = Bw + (size_t)(bn + lr) * K + lk4;

    for (int k0 = 0; k0 < K; k0 += 16) {
        float4 a4 = *(const float4*)(Arow + k0);
        float4 b4 = *(const float4*)(Brow + k0);
        sA[lk4+0][lr] = a4.x; sA[lk4+1][lr] = a4.y;
        sA[lk4+2][lr] = a4.z; sA[lk4+3][lr] = a4.w;
        sB[lk4+0][lr] = b4.x; sB[lk4+1][lr] = b4.y;
        sB[lk4+2][lr] = b4.z; sB[lk4+3][lr] = b4.w;
        __syncthreads();

        #pragma unroll
        for (int k = 0; k < 16; k++) {
            float ra[4], rb[4];
            #pragma unroll
            for (int i = 0; i < 4; i++) ra[i] = sA[k][ty*4 + i];
            #pragma unroll
            for (int j = 0; j < 4; j++) rb[j] = sB[k][tx*4 + j];
            #pragma unroll
            for (int i = 0; i < 4; i++)
                #pragma unroll
                for (int j = 0; j < 4; j++)
                    acc[i][j] += ra[i] * rb[j];
        }
        __syncthreads();
    }

    int row0 = bm + ty*4;
    int col0 = bn + tx*4;
    #pragma unroll
    for (int i = 0; i < 4; i++) {
        int m = row0 + i;
        size_t obase;
        if (EPI == EPI_SCATTER_RES) {
            int bb  = m >> 12;
            int rem = m & 4095;
            int wdx = rem >> 6, n = rem & 63;
            int wh = wdx >> 3, ww = wdx & 7;
            int r  = n   >> 3, s  = n   & 7;
            int hp = ((wh << 3) + r + SHIFT) & 63;
            int wp = ((ww << 3) + s + SHIFT) & 63;
            obase = ((size_t)bb * 4096 + hp * 64 + wp) * CC;
        } else {
            obase = (size_t)m * Nc;
        }
        #pragma unroll
        for (int j = 0; j < 4; j++) {
            int n = col0 + j;
            float v = acc[i][j] + bias[n];
            if (EPI == EPI_GELU) {
                v = 0.5f * v * (1.0f + erff(v * 0.70710678118654752f));
                Cout[obase + n] = v;
            } else if (EPI == EPI_SCATTER_RES) {
                Cout[obase + n] = Res[obase + n] + v;
            } else if (EPI == EPI_RES) {
                Cout[obase + n] = Res[obase + n] + v;
            } else {
                Cout[obase + n] = v;
            }
        }
    }
}

// ---------------- windowed attention (one block per window*head) -----------
__global__ void attn_kernel(const float* __restrict__ qkv,
                            const float* __restrict__ bias_table,
                            const int*   __restrict__ rp_idx,
                            const float* __restrict__ mask,
                            float* __restrict__ outp)
{
    int head = blockIdx.x;          // 0..15
    int bw   = blockIdx.y;          // 0..1023 (b*NWIN + w)
    int wim  = bw & 63;             // window within image
    int tid  = threadIdx.x;         // 256

    __shared__ float qs[64*32];
    __shared__ float ks[64*33];     // padded: avoids 32-way conflict in QK^T
    __shared__ float vs[64*32];
    __shared__ float ss[64*65];

    size_t base = (size_t)bw * 64 * 1536 + head * 32;
    for (int idx = tid; idx < 2048; idx += 256) {
        int n = idx >> 5, d = idx & 31;
        size_t p = base + (size_t)n * 1536 + d;
        qs[n*32 + d] = qkv[p];
        ks[n*33 + d] = qkv[p + 512];
        vs[n*32 + d] = qkv[p + 1024];
    }
    __syncthreads();

    const float* mrow = mask + wim * 4096;
    for (int e = tid; e < 4096; e += 256) {
        int n = e >> 6, mm = e & 63;
        const float* qp = qs + n * 32;
        const float* kp = ks + mm * 33;
        float acc = 0.f;
        #pragma unroll
        for (int d = 0; d < 32; d++) acc += qp[d] * kp[d];
        float rb = bias_table[rp_idx[e] * HEADS + head];
        ss[n*65 + mm] = acc * SCALE_F + rb + mrow[e];
    }
    __syncthreads();

    if (tid < 64) {
        float* row = ss + tid * 65;
        float mx = -1e30f;
        #pragma unroll 8
        for (int j = 0; j < 64; j++) mx = fmaxf(mx, row[j]);
        float sum = 0.f;
        #pragma unroll 8
        for (int j = 0; j < 64; j++) { float ev = expf(row[j] - mx); row[j] = ev; sum += ev; }
        float invs = 1.0f / sum;
        #pragma unroll 8
        for (int j = 0; j < 64; j++) row[j] *= invs;
    }
    __syncthreads();

    for (int e = tid; e < 2048; e += 256) {
        int n = e >> 5, d = e & 31;
        const float* srow = ss + n * 65;
        float acc = 0.f;
        #pragma unroll
        for (int mm = 0; mm < 64; mm++) acc += srow[mm] * vs[mm*32 + d];
        outp[(size_t)(bw * 64 + n) * 512 + head * 32 + d] = acc;
    }
}

// ---------------- launch ----------------
extern "C" void kernel_launch(void* const* d_in, const int* in_sizes, int n_in,
                              void* d_out, int out_size)
{
    const float* x      = (const float*)d_in[0];
    const float* qkv_w  = (const float*)d_in[1];
    const float* qkv_b  = (const float*)d_in[2];
    const float* proj_w = (const float*)d_in[3];
    const float* proj_b = (const float*)d_in[4];
    const float* n1w    = (const float*)d_in[5];
    const float* n1b    = (const float*)d_in[6];
    const float* n2w    = (const float*)d_in[7];
    const float* n2b    = (const float*)d_in[8];
    const float* fc1w   = (const float*)d_in[9];
    const float* fc1b   = (const float*)d_in[10];
    const float* fc2w   = (const float*)d_in[11];
    const float* fc2b   = (const float*)d_in[12];
    const float* rbt    = (const float*)d_in[13];
    const int*   rpi    = (const int*)d_in[14];
    const float* amask  = (const float*)d_in[15];
    float*       out    = (float*)d_out;

    float *hwin, *qkvb, *ob, *x1b, *h2nb, *hidb;
    cudaGetSymbolAddress((void**)&hwin, g_hwin);
    cudaGetSymbolAddress((void**)&qkvb, g_qkv);
    cudaGetSymbolAddress((void**)&ob,   g_o);
    cudaGetSymbolAddress((void**)&x1b,  g_x1);
    cudaGetSymbolAddress((void**)&h2nb, g_h2n);
    cudaGetSymbolAddress((void**)&hidb, g_hid);

    // 1) LN1 + shift + window partition
    ln_kernel<true><<<MTOK, 128>>>(x, n1w, n1b, hwin);

    // 2) QKV GEMM: (65536 x 512) @ (1536 x 512)^T
    gemm64<EPI_PLAIN><<<dim3(1536/64, MTOK/64), 256>>>(
        hwin, qkv_w, qkv_b, qkvb, MTOK, 1536, 512, nullptr);

    // 3) windowed attention
    attn_kernel<<<dim3(HEADS, BB*NWIN), 256>>>(qkvb, rbt, rpi, amask, ob);

    // 4) proj GEMM + window reverse + roll + residual -> x1
    gemm64<EPI_SCATTER_RES><<<dim3(512/64, MTOK/64), 256>>>(
        ob, proj_w, proj_b, x1b, MTOK, 512, 512, x);

    // 5) LN2
    ln_kernel<false><<<MTOK, 128>>>(x1b, n2w, n2b, h2nb);

    // 6) FC1 + GELU
    gemm64<EPI_GELU><<<dim3(2048/64, MTOK/64), 256>>>(
        h2nb, fc1w, fc1b, hidb, MTOK, 2048, 512, nullptr);

    // 7) FC2 + residual -> out
    gemm64<EPI_RES><<<dim3(512/64, MTOK/64), 256>>>(
        hidb, fc2w, fc2b, out, MTOK, 512, 2048, x1b);
}

// round 6
// speedup vs baseline: 2.3040x; 2.3040x over previous
#include <cuda_runtime.h>
#include <math.h>
#include <stdint.h>

// ---------------- static config ----------------
#define BB      16
#define CC      512
#define HEADS   16
#define SHIFT   4
#define HID     2048
#define MTOK    (BB*64*64)   // 65536
#define SCALE_F 0.17677669529663687f
#define EPSF    1e-5f

// ---------------- scratch ----------------
__device__ float g_hwin[(size_t)MTOK * CC];
__device__ float g_qkv [(size_t)MTOK * 3 * CC];
__device__ float g_o   [(size_t)MTOK * CC];
__device__ float g_x1  [(size_t)MTOK * CC];
__device__ float g_h2n [(size_t)MTOK * CC];
__device__ float g_hid [(size_t)MTOK * HID];
__device__ float g_wq  [3*CC*CC];
__device__ float g_wp  [CC*CC];
__device__ float g_w1  [HID*CC];
__device__ float g_w2  [CC*HID];

// ---------------- helpers ----------------
__device__ __forceinline__ float tf32r(float x) {
    float y;
    asm("cvt.rna.tf32.f32 %0, %1;" : "=f"(y) : "f"(x));
    return y;
}
__device__ __forceinline__ uint32_t s2u(const void* p) {
    uint32_t a;
    asm("{ .reg .u64 t; cvta.to.shared.u64 t, %1; cvt.u32.u64 %0, t; }" : "=r"(a) : "l"(p));
    return a;
}
#define CP16(s, g) \
    asm volatile("cp.async.cg.shared.global [%0], [%1], 16;" :: "r"(s), "l"(g))
#define CP_COMMIT() asm volatile("cp.async.commit_group;" ::: "memory")
#define CP_WAIT(N)  asm volatile("cp.async.wait_group %0;" :: "n"(N) : "memory")

__device__ __forceinline__ void mma_tf32(float* c, const uint32_t* a, const uint32_t* b) {
    asm volatile(
        "mma.sync.aligned.m16n8k8.row.col.f32.tf32.tf32.f32 "
        "{%0,%1,%2,%3}, {%4,%5,%6,%7}, {%8,%9}, {%0,%1,%2,%3};"
        : "+f"(c[0]), "+f"(c[1]), "+f"(c[2]), "+f"(c[3])
        : "r"(a[0]), "r"(a[1]), "r"(a[2]), "r"(a[3]), "r"(b[0]), "r"(b[1]));
}

__device__ __forceinline__ size_t scatter_base(int m) {
    int bb = m >> 12, rem = m & 4095;
    int wdx = rem >> 6, n = rem & 63;
    int wh = wdx >> 3, ww = wdx & 7;
    int r = n >> 3, s = n & 7;
    int hp = ((wh << 3) + r + SHIFT) & 63;
    int wp = ((ww << 3) + s + SHIFT) & 63;
    return ((size_t)bb * 4096 + hp * 64 + wp) * CC;
}

// ---------------- weight rounding to tf32 ----------------
__global__ void roundw(const float* __restrict__ w, float* __restrict__ o, int n4)
{
    int i = blockIdx.x * 256 + threadIdx.x;
    if (i < n4) {
        float4 v = ((const float4*)w)[i];
        v.x = tf32r(v.x); v.y = tf32r(v.y); v.z = tf32r(v.z); v.w = tf32r(v.w);
        ((float4*)o)[i] = v;
    }
}

// ---------------- LayerNorm (+ optional shift/window gather), tf32-rounded --
template<bool SHIFTED>
__global__ void ln_kernel(const float* __restrict__ x,
                          const float* __restrict__ w,
                          const float* __restrict__ b,
                          float* __restrict__ out)
{
    __shared__ float sh[4];
    int m   = blockIdx.x;
    int tid = threadIdx.x;          // 128

    size_t dst_row = (size_t)m * CC;
    size_t src_row = dst_row;
    if (SHIFTED) {
        int bb  = m >> 12;
        int rem = m & 4095;
        int wdx = rem >> 6, n = rem & 63;
        int wh = wdx >> 3, ww = wdx & 7;
        int r  = n >> 3, s = n & 7;
        int shp = ((wh << 3) + r + SHIFT) & 63;
        int swp = ((ww << 3) + s + SHIFT) & 63;
        src_row = ((size_t)bb * 4096 + shp * 64 + swp) * CC;
    }

    float4 v = ((const float4*)(x + src_row))[tid];

    float sum = v.x + v.y + v.z + v.w;
    #pragma unroll
    for (int o = 16; o > 0; o >>= 1) sum += __shfl_xor_sync(0xffffffffu, sum, o);
    if ((tid & 31) == 0) sh[tid >> 5] = sum;
    __syncthreads();
    float mean = (sh[0] + sh[1] + sh[2] + sh[3]) * (1.0f / CC);
    __syncthreads();

    float d0 = v.x - mean, d1 = v.y - mean, d2 = v.z - mean, d3 = v.w - mean;
    float sq = d0*d0 + d1*d1 + d2*d2 + d3*d3;
    #pragma unroll
    for (int o = 16; o > 0; o >>= 1) sq += __shfl_xor_sync(0xffffffffu, sq, o);
    if ((tid & 31) == 0) sh[tid >> 5] = sq;
    __syncthreads();
    float var = (sh[0] + sh[1] + sh[2] + sh[3]) * (1.0f / CC);
    float inv = rsqrtf(var + EPSF);

    float4 w4 = ((const float4*)w)[tid];
    float4 b4 = ((const float4*)b)[tid];
    float4 o4;
    o4.x = tf32r(d0 * inv * w4.x + b4.x);
    o4.y = tf32r(d1 * inv * w4.y + b4.y);
    o4.z = tf32r(d2 * inv * w4.z + b4.z);
    o4.w = tf32r(d3 * inv * w4.w + b4.w);
    ((float4*)(out + dst_row))[tid] = o4;
}

// ---------------- tf32 HMMA GEMM: C[M,N] = A[M,K] @ Bw[N,K]^T --------------
#define EPI_PLAIN       0
#define EPI_GELU        1
#define EPI_SCATTER_RES 2
#define EPI_RES         3

// smem: 2 stages x (A 128x36f + B 128x36f)  -> 73728 bytes
#define GSM_STAGE 18432
#define GSM_TOTAL 73728

template<int EPI>
__global__ __launch_bounds__(128, 2)
void tf32_gemm(const float* __restrict__ A,
               const float* __restrict__ Bw,
               const float* __restrict__ bias,
               float* __restrict__ Cout,
               int Nc, int K,
               const float* __restrict__ Res)
{
    extern __shared__ float smem[];   // [A0][B0][A1][B1] each 128*36 floats

    const int tid  = threadIdx.x;     // 128
    const int lane = tid & 31;
    const int w    = tid >> 5;        // 4 warps
    const int wr   = (w >> 1) * 64;   // warp row offset in tile
    const int wc   = (w & 1)  * 64;   // warp col offset in tile
    const int fr   = lane >> 2;       // 0..7
    const int fc   = lane & 3;        // 0..3
    const int bm   = blockIdx.y * 128;
    const int bn   = blockIdx.x * 128;

    float* sA[2] = { smem,                smem + 2*128*36 };
    float* sB[2] = { smem + 128*36,       smem + 3*128*36 };
    uint32_t uA[2] = { s2u(sA[0]), s2u(sA[1]) };
    uint32_t uB[2] = { s2u(sB[0]), s2u(sB[1]) };

    const float* gA = A  + (size_t)(bm + tid) * K;
    const float* gB = Bw + (size_t)(bn + tid) * K;

    float acc[4][8][4];
    #pragma unroll
    for (int i = 0; i < 4; i++)
        #pragma unroll
        for (int j = 0; j < 8; j++)
            #pragma unroll
            for (int q = 0; q < 4; q++) acc[i][j][q] = 0.f;

    const int nch = K >> 5;           // K/32 chunks

    // prefetch stage 0
    {
        uint32_t da = uA[0] + tid * 144, db = uB[0] + tid * 144;
        #pragma unroll
        for (int j = 0; j < 8; j++) {
            CP16(da + j * 16, gA + j * 4);
            CP16(db + j * 16, gB + j * 4);
        }
        CP_COMMIT();
    }

    for (int c = 0; c < nch; c++) {
        const int st = c & 1;
        if (c + 1 < nch) {
            const int ns = st ^ 1;
            const float* pa = gA + (c + 1) * 32;
            const float* pb = gB + (c + 1) * 32;
            uint32_t da = uA[ns] + tid * 144, db = uB[ns] + tid * 144;
            #pragma unroll
            for (int j = 0; j < 8; j++) {
                CP16(da + j * 16, pa + j * 4);
                CP16(db + j * 16, pb + j * 4);
            }
            CP_COMMIT();
            CP_WAIT(1);
        } else {
            CP_WAIT(0);
        }
        __syncthreads();

        const float* cA = sA[st];
        const float* cB = sB[st];
        #pragma unroll
        for (int k8 = 0; k8 < 4; k8++) {
            const int kk = k8 * 8;
            uint32_t a[4][4], b[8][2];
            #pragma unroll
            for (int mb = 0; mb < 4; mb++) {
                const float* pa = cA + (wr + mb * 16 + fr) * 36 + kk + fc;
                a[mb][0] = __float_as_uint(pa[0]);
                a[mb][1] = __float_as_uint(pa[8 * 36]);
                a[mb][2] = __float_as_uint(pa[4]);
                a[mb][3] = __float_as_uint(pa[8 * 36 + 4]);
            }
            #pragma unroll
            for (int nb = 0; nb < 8; nb++) {
                const float* pb = cB + (wc + nb * 8 + fr) * 36 + kk + fc;
                b[nb][0] = __float_as_uint(pb[0]);
                b[nb][1] = __float_as_uint(pb[4]);
            }
            #pragma unroll
            for (int mb = 0; mb < 4; mb++)
                #pragma unroll
                for (int nb = 0; nb < 8; nb++)
                    mma_tf32(acc[mb][nb], a[mb], b[nb]);
        }
        __syncthreads();
    }

    // ---------------- epilogue ----------------
    #pragma unroll
    for (int mb = 0; mb < 4; mb++) {
        const int m0 = bm + wr + mb * 16 + fr;
        const int m1 = m0 + 8;
        size_t ob0, ob1;
        if (EPI == EPI_SCATTER_RES) { ob0 = scatter_base(m0); ob1 = scatter_base(m1); }
        else                        { ob0 = (size_t)m0 * Nc;  ob1 = (size_t)m1 * Nc; }
        #pragma unroll
        for (int nb = 0; nb < 8; nb++) {
            const int n0 = bn + wc + nb * 8 + 2 * fc;
            float2 bb = *(const float2*)(bias + n0);
            float v0 = acc[mb][nb][0] + bb.x;
            float v1 = acc[mb][nb][1] + bb.y;
            float v2 = acc[mb][nb][2] + bb.x;
            float v3 = acc[mb][nb][3] + bb.y;
            if (EPI == EPI_GELU) {
                v0 = tf32r(0.5f * v0 * (1.0f + erff(v0 * 0.70710678118654752f)));
                v1 = tf32r(0.5f * v1 * (1.0f + erff(v1 * 0.70710678118654752f)));
                v2 = tf32r(0.5f * v2 * (1.0f + erff(v2 * 0.70710678118654752f)));
                v3 = tf32r(0.5f * v3 * (1.0f + erff(v3 * 0.70710678118654752f)));
            } else if (EPI == EPI_SCATTER_RES || EPI == EPI_RES) {
                float2 r0 = *(const float2*)(Res + ob0 + n0);
                float2 r1 = *(const float2*)(Res + ob1 + n0);
                v0 += r0.x; v1 += r0.y; v2 += r1.x; v3 += r1.y;
            }
            *(float2*)(Cout + ob0 + n0) = make_float2(v0, v1);
            *(float2*)(Cout + ob1 + n0) = make_float2(v2, v3);
        }
    }
}

// ---------------- windowed attention (tf32-rounded output) -----------------
__global__ void attn_kernel(const float* __restrict__ qkv,
                            const float* __restrict__ bias_table,
                            const int*   __restrict__ rp_idx,
                            const float* __restrict__ mask,
                            float* __restrict__ outp)
{
    int head = blockIdx.x;
    int bw   = blockIdx.y;
    int wim  = bw & 63;
    int tid  = threadIdx.x;     // 256

    __shared__ float qs[64*32];
    __shared__ float ks[64*33];
    __shared__ float vs[64*32];
    __shared__ float ss[64*65];

    size_t base = (size_t)bw * 64 * 1536 + head * 32;
    for (int idx = tid; idx < 2048; idx += 256) {
        int n = idx >> 5, d = idx & 31;
        size_t p = base + (size_t)n * 1536 + d;
        qs[n*32 + d] = qkv[p];
        ks[n*33 + d] = qkv[p + 512];
        vs[n*32 + d] = qkv[p + 1024];
    }
    __syncthreads();

    const float* mrow = mask + wim * 4096;
    for (int e = tid; e < 4096; e += 256) {
        int n = e >> 6, mm = e & 63;
        const float* qp = qs + n * 32;
        const float* kp = ks + mm * 33;
        float acc = 0.f;
        #pragma unroll
        for (int d = 0; d < 32; d++) acc += qp[d] * kp[d];
        float rb = bias_table[rp_idx[e] * HEADS + head];
        ss[n*65 + mm] = acc * SCALE_F + rb + mrow[e];
    }
    __syncthreads();

    if (tid < 64) {
        float* row = ss + tid * 65;
        float mx = -1e30f;
        #pragma unroll 8
        for (int j = 0; j < 64; j++) mx = fmaxf(mx, row[j]);
        float sum = 0.f;
        #pragma unroll 8
        for (int j = 0; j < 64; j++) { float ev = expf(row[j] - mx); row[j] = ev; sum += ev; }
        float invs = 1.0f / sum;
        #pragma unroll 8
        for (int j = 0; j < 64; j++) row[j] *= invs;
    }
    __syncthreads();

    for (int e = tid; e < 2048; e += 256) {
        int n = e >> 5, d = e & 31;
        const float* srow = ss + n * 65;
        float acc = 0.f;
        #pragma unroll
        for (int mm = 0; mm < 64; mm++) acc += srow[mm] * vs[mm*32 + d];
        outp[(size_t)(bw * 64 + n) * 512 + head * 32 + d] = tf32r(acc);
    }
}

// ---------------- launch ----------------
extern "C" void kernel_launch(void* const* d_in, const int* in_sizes, int n_in,
                              void* d_out, int out_size)
{
    const float* x      = (const float*)d_in[0];
    const float* qkv_w  = (const float*)d_in[1];
    const float* qkv_b  = (const float*)d_in[2];
    const float* proj_w = (const float*)d_in[3];
    const float* proj_b = (const float*)d_in[4];
    const float* n1w    = (const float*)d_in[5];
    const float* n1b    = (const float*)d_in[6];
    const float* n2w    = (const float*)d_in[7];
    const float* n2b    = (const float*)d_in[8];
    const float* fc1w   = (const float*)d_in[9];
    const float* fc1b   = (const float*)d_in[10];
    const float* fc2w   = (const float*)d_in[11];
    const float* fc2b   = (const float*)d_in[12];
    const float* rbt    = (const float*)d_in[13];
    const int*   rpi    = (const int*)d_in[14];
    const float* amask  = (const float*)d_in[15];
    float*       out    = (float*)d_out;

    float *hwin, *qkvb, *ob, *x1b, *h2nb, *hidb, *wq, *wp, *w1, *w2;
    cudaGetSymbolAddress((void**)&hwin, g_hwin);
    cudaGetSymbolAddress((void**)&qkvb, g_qkv);
    cudaGetSymbolAddress((void**)&ob,   g_o);
    cudaGetSymbolAddress((void**)&x1b,  g_x1);
    cudaGetSymbolAddress((void**)&h2nb, g_h2n);
    cudaGetSymbolAddress((void**)&hidb, g_hid);
    cudaGetSymbolAddress((void**)&wq,   g_wq);
    cudaGetSymbolAddress((void**)&wp,   g_wp);
    cudaGetSymbolAddress((void**)&w1,   g_w1);
    cudaGetSymbolAddress((void**)&w2,   g_w2);

    cudaFuncSetAttribute(tf32_gemm<EPI_PLAIN>,       cudaFuncAttributeMaxDynamicSharedMemorySize, GSM_TOTAL);
    cudaFuncSetAttribute(tf32_gemm<EPI_GELU>,        cudaFuncAttributeMaxDynamicSharedMemorySize, GSM_TOTAL);
    cudaFuncSetAttribute(tf32_gemm<EPI_SCATTER_RES>, cudaFuncAttributeMaxDynamicSharedMemorySize, GSM_TOTAL);
    cudaFuncSetAttribute(tf32_gemm<EPI_RES>,         cudaFuncAttributeMaxDynamicSharedMemorySize, GSM_TOTAL);

    // 0) round weights to tf32
    roundw<<<(3*CC*CC/4 + 255)/256, 256>>>(qkv_w,  wq, 3*CC*CC/4);
    roundw<<<(CC*CC/4   + 255)/256, 256>>>(proj_w, wp, CC*CC/4);
    roundw<<<(HID*CC/4  + 255)/256, 256>>>(fc1w,   w1, HID*CC/4);
    roundw<<<(CC*HID/4  + 255)/256, 256>>>(fc2w,   w2, CC*HID/4);

    // 1) LN1 + shift + window partition (tf32-rounded)
    ln_kernel<true><<<MTOK, 128>>>(x, n1w, n1b, hwin);

    // 2) QKV GEMM
    tf32_gemm<EPI_PLAIN><<<dim3(1536/128, MTOK/128), 128, GSM_TOTAL>>>(
        hwin, wq, qkv_b, qkvb, 1536, 512, nullptr);

    // 3) windowed attention
    attn_kernel<<<dim3(HEADS, BB*64), 256>>>(qkvb, rbt, rpi, amask, ob);

    // 4) proj GEMM + window reverse + roll + residual -> x1
    tf32_gemm<EPI_SCATTER_RES><<<dim3(512/128, MTOK/128), 128, GSM_TOTAL>>>(
        ob, wp, proj_b, x1b, 512, 512, x);

    // 5) LN2 (tf32-rounded)
    ln_kernel<false><<<MTOK, 128>>>(x1b, n2w, n2b, h2nb);

    // 6) FC1 + GELU (tf32-rounded)
    tf32_gemm<EPI_GELU><<<dim3(2048/128, MTOK/128), 128, GSM_TOTAL>>>(
        h2nb, w1, fc1b, hidb, 2048, 512, nullptr);

    // 7) FC2 + residual -> out
    tf32_gemm<EPI_RES><<<dim3(512/128, MTOK/128), 128, GSM_TOTAL>>>(
        hidb, w2, fc2b, out, 512, 2048, x1b);
}

// round 7
// speedup vs baseline: 4.4521x; 1.9323x over previous
#include <cuda_runtime.h>
#include <cuda_fp16.h>
#include <math.h>
#include <stdint.h>

// ---------------- static config ----------------
#define BB      16
#define CC      512
#define HEADS   16
#define SHIFT   4
#define HID     2048
#define MTOK    (BB*64*64)   // 65536
#define SCALE_F 0.17677669529663687f
#define EPSF    1e-5f

// ---------------- scratch ----------------
__device__ __half g_hwin[(size_t)MTOK * CC];
__device__ __half g_qkv [(size_t)MTOK * 3 * CC];
__device__ __half g_o   [(size_t)MTOK * CC];
__device__ float  g_x1  [(size_t)MTOK * CC];
__device__ __half g_h2n [(size_t)MTOK * CC];
__device__ __half g_hid [(size_t)MTOK * HID];
__device__ __half g_wq  [3*CC*CC];
__device__ __half g_wp  [CC*CC];
__device__ __half g_w1  [HID*CC];
__device__ __half g_w2  [CC*HID];

// ---------------- helpers ----------------
__device__ __forceinline__ uint32_t s2u(const void* p) {
    uint32_t a;
    asm("{ .reg .u64 t; cvta.to.shared.u64 t, %1; cvt.u32.u64 %0, t; }" : "=r"(a) : "l"(p));
    return a;
}
#define CP16(s, g) \
    asm volatile("cp.async.cg.shared.global [%0], [%1], 16;" :: "r"(s), "l"(g))
#define CP_COMMIT() asm volatile("cp.async.commit_group;" ::: "memory")
#define CP_WAIT(N)  asm volatile("cp.async.wait_group %0;" :: "n"(N) : "memory")

#define LDSM4(r, a) \
    asm volatile("ldmatrix.sync.aligned.m8n8.x4.shared.b16 {%0,%1,%2,%3}, [%4];" \
        : "=r"((r)[0]), "=r"((r)[1]), "=r"((r)[2]), "=r"((r)[3]) : "r"(a))

__device__ __forceinline__ void mma_f16(float* c, const uint32_t* a, const uint32_t* b) {
    asm volatile(
        "mma.sync.aligned.m16n8k16.row.col.f32.f16.f16.f32 "
        "{%0,%1,%2,%3}, {%4,%5,%6,%7}, {%8,%9}, {%0,%1,%2,%3};"
        : "+f"(c[0]), "+f"(c[1]), "+f"(c[2]), "+f"(c[3])
        : "r"(a[0]), "r"(a[1]), "r"(a[2]), "r"(a[3]), "r"(b[0]), "r"(b[1]));
}

__device__ __forceinline__ size_t scatter_base(int m) {
    int bb = m >> 12, rem = m & 4095;
    int wdx = rem >> 6, n = rem & 63;
    int wh = wdx >> 3, ww = wdx & 7;
    int r = n >> 3, s = n & 7;
    int hp = ((wh << 3) + r + SHIFT) & 63;
    int wp = ((ww << 3) + s + SHIFT) & 63;
    return ((size_t)bb * 4096 + hp * 64 + wp) * CC;
}

// ---------------- weight conversion fp32 -> fp16 ----------------
__global__ void cvtw(const float* __restrict__ w, __half* __restrict__ o, int n4)
{
    int i = blockIdx.x * 256 + threadIdx.x;
    if (i < n4) {
        float4 v = ((const float4*)w)[i];
        __half2 a = __floats2half2_rn(v.x, v.y);
        __half2 b = __floats2half2_rn(v.z, v.w);
        uint2 pk = { *(uint32_t*)&a, *(uint32_t*)&b };
        ((uint2*)o)[i] = pk;
    }
}

// ---------------- LayerNorm (+shift/window gather), fp16 out ---------------
template<bool SHIFTED>
__global__ void ln_kernel(const float* __restrict__ x,
                          const float* __restrict__ w,
                          const float* __restrict__ b,
                          __half* __restrict__ out)
{
    __shared__ float sh[4];
    int m   = blockIdx.x;
    int tid = threadIdx.x;          // 128

    size_t dst_row = (size_t)m * CC;
    size_t src_row = dst_row;
    if (SHIFTED) {
        int bb  = m >> 12;
        int rem = m & 4095;
        int wdx = rem >> 6, n = rem & 63;
        int wh = wdx >> 3, ww = wdx & 7;
        int r  = n >> 3, s = n & 7;
        int shp = ((wh << 3) + r + SHIFT) & 63;
        int swp = ((ww << 3) + s + SHIFT) & 63;
        src_row = ((size_t)bb * 4096 + shp * 64 + swp) * CC;
    }

    float4 v = ((const float4*)(x + src_row))[tid];

    float sum = v.x + v.y + v.z + v.w;
    #pragma unroll
    for (int o = 16; o > 0; o >>= 1) sum += __shfl_xor_sync(0xffffffffu, sum, o);
    if ((tid & 31) == 0) sh[tid >> 5] = sum;
    __syncthreads();
    float mean = (sh[0] + sh[1] + sh[2] + sh[3]) * (1.0f / CC);
    __syncthreads();

    float d0 = v.x - mean, d1 = v.y - mean, d2 = v.z - mean, d3 = v.w - mean;
    float sq = d0*d0 + d1*d1 + d2*d2 + d3*d3;
    #pragma unroll
    for (int o = 16; o > 0; o >>= 1) sq += __shfl_xor_sync(0xffffffffu, sq, o);
    if ((tid & 31) == 0) sh[tid >> 5] = sq;
    __syncthreads();
    float var = (sh[0] + sh[1] + sh[2] + sh[3]) * (1.0f / CC);
    float inv = rsqrtf(var + EPSF);

    float4 w4 = ((const float4*)w)[tid];
    float4 b4 = ((const float4*)b)[tid];
    __half2 h01 = __floats2half2_rn(d0 * inv * w4.x + b4.x, d1 * inv * w4.y + b4.y);
    __half2 h23 = __floats2half2_rn(d2 * inv * w4.z + b4.z, d3 * inv * w4.w + b4.w);
    uint2 pk = { *(uint32_t*)&h01, *(uint32_t*)&h23 };
    *(uint2*)(out + dst_row + tid * 4) = pk;
}

// ---------------- fp16 HMMA GEMM: C[M,N] = A[M,K] @ Bw[N,K]^T --------------
#define EPI_PLAIN       0
#define EPI_GELU        1
#define EPI_SCATTER_RES 2
#define EPI_RES         3

// smem: 3 stages x (A 128x80B + B 128x80B) = 3 x 20480 = 61440 bytes
#define HSTAGE    20480
#define HSM_TOTAL 61440

__device__ __forceinline__ void cp_stage(uint32_t da, uint32_t db,
                                         const __half* pa, const __half* pb) {
    #pragma unroll
    for (int j = 0; j < 4; j++) {
        CP16(da + j * 16, pa + j * 8);
        CP16(db + j * 16, pb + j * 8);
    }
    CP_COMMIT();
}

template<int EPI>
__global__ __launch_bounds__(128, 2)
void h_gemm(const __half* __restrict__ A,
            const __half* __restrict__ Bw,
            const float* __restrict__ bias,
            float* __restrict__ outf,
            __half* __restrict__ outh,
            int Nc, int K,
            const float* __restrict__ Res)
{
    extern __shared__ char smem[];

    const int tid  = threadIdx.x;     // 128
    const int lane = tid & 31;
    const int w    = tid >> 5;        // 4 warps
    const int wr   = (w >> 1) * 64;
    const int wc   = (w & 1)  * 64;
    const int bm   = blockIdx.y * 128;
    const int bn   = blockIdx.x * 128;

    const uint32_t sb = s2u(smem);

    // per-thread cp.async source/dest (thread t owns tile row t, 64B of K)
    const __half* gA = A  + (size_t)(bm + tid) * K;
    const __half* gB = Bw + (size_t)(bn + tid) * K;
    const uint32_t rowA = sb + tid * 80;
    const uint32_t rowB = sb + 10240 + tid * 80;

    float acc[4][8][4];
    #pragma unroll
    for (int i = 0; i < 4; i++)
        #pragma unroll
        for (int j = 0; j < 8; j++)
            #pragma unroll
            for (int q = 0; q < 4; q++) acc[i][j][q] = 0.f;

    const int nch = K >> 5;           // K/32 chunks

    // ldmatrix fragment offsets (relative to stage base)
    const int tile = lane >> 3, rit = lane & 7;
    uint32_t aOff[4], bOff[4];
    #pragma unroll
    for (int mb = 0; mb < 4; mb++)
        aOff[mb] = (uint32_t)((wr + mb * 16 + (tile & 1) * 8 + rit) * 80 + (tile >> 1) * 16);
    #pragma unroll
    for (int p = 0; p < 4; p++)
        bOff[p] = (uint32_t)(10240 + (wc + p * 16 + (tile >> 1) * 8 + rit) * 80 + (tile & 1) * 16);

    // prologue: stages 0,1
    cp_stage(rowA, rowB, gA, gB);
    cp_stage(rowA + HSTAGE, rowB + HSTAGE, gA + 32, gB + 32);

    int st_ld = 2;   // next stage to fill
    for (int c = 0; c < nch; c++) {
        CP_WAIT(1);
        __syncthreads();
        if (c + 2 < nch) {
            cp_stage(rowA + st_ld * HSTAGE, rowB + st_ld * HSTAGE,
                     gA + (c + 2) * 32, gB + (c + 2) * 32);
        }
        const uint32_t stb = sb + (uint32_t)((c == 0) ? 0 : (c % 3)) * HSTAGE;
        #pragma unroll
        for (int kk = 0; kk < 2; kk++) {
            uint32_t a[4][4], b[4][4];
            #pragma unroll
            for (int mb = 0; mb < 4; mb++) LDSM4(a[mb], stb + aOff[mb] + kk * 32);
            #pragma unroll
            for (int p = 0; p < 4; p++)    LDSM4(b[p],  stb + bOff[p] + kk * 32);
            #pragma unroll
            for (int mb = 0; mb < 4; mb++)
                #pragma unroll
                for (int nb = 0; nb < 8; nb++)
                    mma_f16(acc[mb][nb], a[mb], &b[nb >> 1][(nb & 1) * 2]);
        }
        st_ld = (st_ld == 2) ? 0 : st_ld + 1;
    }

    // ---------------- epilogue ----------------
    const int fr = lane >> 2, fc = lane & 3;
    #pragma unroll
    for (int mb = 0; mb < 4; mb++) {
        const int m0 = bm + wr + mb * 16 + fr;
        const int m1 = m0 + 8;
        size_t ob0, ob1;
        if (EPI == EPI_SCATTER_RES) { ob0 = scatter_base(m0); ob1 = scatter_base(m1); }
        else                        { ob0 = (size_t)m0 * Nc;  ob1 = (size_t)m1 * Nc; }
        #pragma unroll
        for (int nb = 0; nb < 8; nb++) {
            const int n0 = bn + wc + nb * 8 + 2 * fc;
            float2 bb = *(const float2*)(bias + n0);
            float v0 = acc[mb][nb][0] + bb.x;
            float v1 = acc[mb][nb][1] + bb.y;
            float v2 = acc[mb][nb][2] + bb.x;
            float v3 = acc[mb][nb][3] + bb.y;
            if (EPI == EPI_GELU) {
                v0 = 0.5f * v0 * (1.0f + erff(v0 * 0.70710678118654752f));
                v1 = 0.5f * v1 * (1.0f + erff(v1 * 0.70710678118654752f));
                v2 = 0.5f * v2 * (1.0f + erff(v2 * 0.70710678118654752f));
                v3 = 0.5f * v3 * (1.0f + erff(v3 * 0.70710678118654752f));
            } else if (EPI == EPI_SCATTER_RES || EPI == EPI_RES) {
                float2 r0 = *(const float2*)(Res + ob0 + n0);
                float2 r1 = *(const float2*)(Res + ob1 + n0);
                v0 += r0.x; v1 += r0.y; v2 += r1.x; v3 += r1.y;
            }
            if (EPI == EPI_PLAIN || EPI == EPI_GELU) {
                __half2 h0 = __floats2half2_rn(v0, v1);
                __half2 h1 = __floats2half2_rn(v2, v3);
                *(uint32_t*)(outh + ob0 + n0) = *(uint32_t*)&h0;
                *(uint32_t*)(outh + ob1 + n0) = *(uint32_t*)&h1;
            } else {
                *(float2*)(outf + ob0 + n0) = make_float2(v0, v1);
                *(float2*)(outf + ob1 + n0) = make_float2(v2, v3);
            }
        }
    }
}

// ---------------- windowed attention (fp16 qkv in, fp16 out) ---------------
__global__ void attn_kernel(const __half* __restrict__ qkv,
                            const float* __restrict__ bias_table,
                            const int*   __restrict__ rp_idx,
                            const float* __restrict__ mask,
                            __half* __restrict__ outp)
{
    int head = blockIdx.x;
    int bw   = blockIdx.y;
    int wim  = bw & 63;
    int tid  = threadIdx.x;     // 256

    __shared__ float qs[64*32];
    __shared__ float ks[64*33];
    __shared__ float vs[64*32];
    __shared__ float ss[64*65];

    size_t base = (size_t)bw * 64 * 1536 + head * 32;
    for (int idx = tid; idx < 1024; idx += 256) {
        int n = idx >> 4, d2 = idx & 15;
        size_t p = base + (size_t)n * 1536 + d2 * 2;
        float2 qf = __half22float2(*(const __half2*)(qkv + p));
        float2 kf = __half22float2(*(const __half2*)(qkv + p + 512));
        float2 vf = __half22float2(*(const __half2*)(qkv + p + 1024));
        qs[n*32 + 2*d2]     = qf.x; qs[n*32 + 2*d2 + 1] = qf.y;
        ks[n*33 + 2*d2]     = kf.x; ks[n*33 + 2*d2 + 1] = kf.y;
        vs[n*32 + 2*d2]     = vf.x; vs[n*32 + 2*d2 + 1] = vf.y;
    }
    __syncthreads();

    const float* mrow = mask + wim * 4096;
    for (int e = tid; e < 4096; e += 256) {
        int n = e >> 6, mm = e & 63;
        const float* qp = qs + n * 32;
        const float* kp = ks + mm * 33;
        float acc = 0.f;
        #pragma unroll
        for (int d = 0; d < 32; d++) acc += qp[d] * kp[d];
        float rb = bias_table[rp_idx[e] * HEADS + head];
        ss[n*65 + mm] = acc * SCALE_F + rb + mrow[e];
    }
    __syncthreads();

    if (tid < 64) {
        float* row = ss + tid * 65;
        float mx = -1e30f;
        #pragma unroll 8
        for (int j = 0; j < 64; j++) mx = fmaxf(mx, row[j]);
        float sum = 0.f;
        #pragma unroll 8
        for (int j = 0; j < 64; j++) { float ev = __expf(row[j] - mx); row[j] = ev; sum += ev; }
        float invs = 1.0f / sum;
        #pragma unroll 8
        for (int j = 0; j < 64; j++) row[j] *= invs;
    }
    __syncthreads();

    for (int e = tid; e < 2048; e += 256) {
        int n = e >> 5, d = e & 31;
        const float* srow = ss + n * 65;
        float acc = 0.f;
        #pragma unroll
        for (int mm = 0; mm < 64; mm++) acc += srow[mm] * vs[mm*32 + d];
        outp[(size_t)(bw * 64 + n) * 512 + head * 32 + d] = __float2half_rn(acc);
    }
}

// ---------------- launch ----------------
extern "C" void kernel_launch(void* const* d_in, const int* in_sizes, int n_in,
                              void* d_out, int out_size)
{
    const float* x      = (const float*)d_in[0];
    const float* qkv_w  = (const float*)d_in[1];
    const float* qkv_b  = (const float*)d_in[2];
    const float* proj_w = (const float*)d_in[3];
    const float* proj_b = (const float*)d_in[4];
    const float* n1w    = (const float*)d_in[5];
    const float* n1b    = (const float*)d_in[6];
    const float* n2w    = (const float*)d_in[7];
    const float* n2b    = (const float*)d_in[8];
    const float* fc1w   = (const float*)d_in[9];
    const float* fc1b   = (const float*)d_in[10];
    const float* fc2w   = (const float*)d_in[11];
    const float* fc2b   = (const float*)d_in[12];
    const float* rbt    = (const float*)d_in[13];
    const int*   rpi    = (const int*)d_in[14];
    const float* amask  = (const float*)d_in[15];
    float*       out    = (float*)d_out;

    __half *hwin, *qkvb, *ob, *h2nb, *hidb, *wq, *wp, *w1, *w2;
    float *x1b;
    cudaGetSymbolAddress((void**)&hwin, g_hwin);
    cudaGetSymbolAddress((void**)&qkvb, g_qkv);
    cudaGetSymbolAddress((void**)&ob,   g_o);
    cudaGetSymbolAddress((void**)&x1b,  g_x1);
    cudaGetSymbolAddress((void**)&h2nb, g_h2n);
    cudaGetSymbolAddress((void**)&hidb, g_hid);
    cudaGetSymbolAddress((void**)&wq,   g_wq);
    cudaGetSymbolAddress((void**)&wp,   g_wp);
    cudaGetSymbolAddress((void**)&w1,   g_w1);
    cudaGetSymbolAddress((void**)&w2,   g_w2);

    cudaFuncSetAttribute(h_gemm<EPI_PLAIN>,       cudaFuncAttributeMaxDynamicSharedMemorySize, HSM_TOTAL);
    cudaFuncSetAttribute(h_gemm<EPI_GELU>,        cudaFuncAttributeMaxDynamicSharedMemorySize, HSM_TOTAL);
    cudaFuncSetAttribute(h_gemm<EPI_SCATTER_RES>, cudaFuncAttributeMaxDynamicSharedMemorySize, HSM_TOTAL);
    cudaFuncSetAttribute(h_gemm<EPI_RES>,         cudaFuncAttributeMaxDynamicSharedMemorySize, HSM_TOTAL);

    // 0) convert weights to fp16
    cvtw<<<(3*CC*CC/4 + 255)/256, 256>>>(qkv_w,  wq, 3*CC*CC/4);
    cvtw<<<(CC*CC/4   + 255)/256, 256>>>(proj_w, wp, CC*CC/4);
    cvtw<<<(HID*CC/4  + 255)/256, 256>>>(fc1w,   w1, HID*CC/4);
    cvtw<<<(CC*HID/4  + 255)/256, 256>>>(fc2w,   w2, CC*HID/4);

    // 1) LN1 + shift + window partition -> fp16
    ln_kernel<true><<<MTOK, 128>>>(x, n1w, n1b, hwin);

    // 2) QKV GEMM
    h_gemm<EPI_PLAIN><<<dim3(1536/128, MTOK/128), 128, HSM_TOTAL>>>(
        hwin, wq, qkv_b, nullptr, qkvb, 1536, 512, nullptr);

    // 3) windowed attention
    attn_kernel<<<dim3(HEADS, BB*64), 256>>>(qkvb, rbt, rpi, amask, ob);

    // 4) proj GEMM + window reverse + roll + residual -> x1 (fp32)
    h_gemm<EPI_SCATTER_RES><<<dim3(512/128, MTOK/128), 128, HSM_TOTAL>>>(
        ob, wp, proj_b, x1b, nullptr, 512, 512, x);

    // 5) LN2 -> fp16
    ln_kernel<false><<<MTOK, 128>>>(x1b, n2w, n2b, h2nb);

    // 6) FC1 + GELU -> fp16
    h_gemm<EPI_GELU><<<dim3(2048/128, MTOK/128), 128, HSM_TOTAL>>>(
        h2nb, w1, fc1b, nullptr, hidb, 2048, 512, nullptr);

    // 7) FC2 + residual -> out (fp32)
    h_gemm<EPI_RES><<<dim3(512/128, MTOK/128), 128, HSM_TOTAL>>>(
        hidb, w2, fc2b, out, nullptr, 512, 2048, x1b);
}

// round 8
// speedup vs baseline: 5.3837x; 1.2093x over previous
#include <cuda_runtime.h>
#include <cuda_fp16.h>
#include <math.h>
#include <stdint.h>

// ---------------- static config ----------------
#define BB      16
#define CC      512
#define HEADS   16
#define SHIFT   4
#define HID     2048
#define MTOK    (BB*64*64)   // 65536
#define SCALE_F 0.17677669529663687f
#define EPSF    1e-5f

// ---------------- scratch ----------------
__device__ __half g_hwin[(size_t)MTOK * CC];
__device__ __half g_qkv [(size_t)MTOK * 3 * CC];
__device__ __half g_o   [(size_t)MTOK * CC];
__device__ float  g_x1  [(size_t)MTOK * CC];
__device__ __half g_h2n [(size_t)MTOK * CC];
__device__ __half g_hid [(size_t)MTOK * HID];
__device__ __half g_wq  [3*CC*CC];
__device__ __half g_wp  [CC*CC];
__device__ __half g_w1  [HID*CC];
__device__ __half g_w2  [CC*HID];
__device__ float  g_bm  [(size_t)1024 * 4096];   // (head*64+wim) x (n*64+m) bias+mask

// ---------------- helpers ----------------
__device__ __forceinline__ uint32_t s2u(const void* p) {
    uint32_t a;
    asm("{ .reg .u64 t; cvta.to.shared.u64 t, %1; cvt.u32.u64 %0, t; }" : "=r"(a) : "l"(p));
    return a;
}
#define CP16(s, g) \
    asm volatile("cp.async.cg.shared.global [%0], [%1], 16;" :: "r"(s), "l"(g))
#define CP_COMMIT() asm volatile("cp.async.commit_group;" ::: "memory")
#define CP_WAIT(N)  asm volatile("cp.async.wait_group %0;" :: "n"(N) : "memory")

#define LDSM4(r, a) \
    asm volatile("ldmatrix.sync.aligned.m8n8.x4.shared.b16 {%0,%1,%2,%3}, [%4];" \
        : "=r"((r)[0]), "=r"((r)[1]), "=r"((r)[2]), "=r"((r)[3]) : "r"(a))
#define LDSM4T(r, a) \
    asm volatile("ldmatrix.sync.aligned.m8n8.x4.trans.shared.b16 {%0,%1,%2,%3}, [%4];" \
        : "=r"((r)[0]), "=r"((r)[1]), "=r"((r)[2]), "=r"((r)[3]) : "r"(a))

__device__ __forceinline__ void mma_f16(float* c, const uint32_t* a, const uint32_t* b) {
    asm volatile(
        "mma.sync.aligned.m16n8k16.row.col.f32.f16.f16.f32 "
        "{%0,%1,%2,%3}, {%4,%5,%6,%7}, {%8,%9}, {%0,%1,%2,%3};"
        : "+f"(c[0]), "+f"(c[1]), "+f"(c[2]), "+f"(c[3])
        : "r"(a[0]), "r"(a[1]), "r"(a[2]), "r"(a[3]), "r"(b[0]), "r"(b[1]));
}

__device__ __forceinline__ uint32_t pkh2(float a, float b) {
    __half2 t = __floats2half2_rn(a, b);
    return *reinterpret_cast<uint32_t*>(&t);
}

__device__ __forceinline__ size_t scatter_base(int m) {
    int bb = m >> 12, rem = m & 4095;
    int wdx = rem >> 6, n = rem & 63;
    int wh = wdx >> 3, ww = wdx & 7;
    int r = n >> 3, s = n & 7;
    int hp = ((wh << 3) + r + SHIFT) & 63;
    int wp = ((ww << 3) + s + SHIFT) & 63;
    return ((size_t)bb * 4096 + hp * 64 + wp) * CC;
}

// ---------------- weight conversion fp32 -> fp16 ----------------
__global__ void cvtw(const float* __restrict__ w, __half* __restrict__ o, int n4)
{
    int i = blockIdx.x * 256 + threadIdx.x;
    if (i < n4) {
        float4 v = ((const float4*)w)[i];
        __half2 a = __floats2half2_rn(v.x, v.y);
        __half2 b = __floats2half2_rn(v.z, v.w);
        uint2 pk = { *(uint32_t*)&a, *(uint32_t*)&b };
        ((uint2*)o)[i] = pk;
    }
}

// ---------------- bias+mask precompute: g_bm[head*64+wim][n*64+m] ----------
__global__ void bmprep(const float* __restrict__ mask,
                       const float* __restrict__ rbt,
                       const int*   __restrict__ rpi,
                       float* __restrict__ bm)
{
    int hw   = blockIdx.x;          // 0..1023
    int head = hw >> 6, wim = hw & 63;
    const float* mrow = mask + wim * 4096;
    float* dst = bm + (size_t)hw * 4096;
    for (int e = threadIdx.x; e < 4096; e += 256)
        dst[e] = mrow[e] + rbt[rpi[e] * HEADS + head];
}

// ---------------- LayerNorm (+shift/window gather), fp16 out ---------------
template<bool SHIFTED>
__global__ void ln_kernel(const float* __restrict__ x,
                          const float* __restrict__ w,
                          const float* __restrict__ b,
                          __half* __restrict__ out)
{
    __shared__ float sh[4];
    int m   = blockIdx.x;
    int tid = threadIdx.x;          // 128

    size_t dst_row = (size_t)m * CC;
    size_t src_row = dst_row;
    if (SHIFTED) {
        int bb  = m >> 12;
        int rem = m & 4095;
        int wdx = rem >> 6, n = rem & 63;
        int wh = wdx >> 3, ww = wdx & 7;
        int r  = n >> 3, s = n & 7;
        int shp = ((wh << 3) + r + SHIFT) & 63;
        int swp = ((ww << 3) + s + SHIFT) & 63;
        src_row = ((size_t)bb * 4096 + shp * 64 + swp) * CC;
    }

    float4 v = ((const float4*)(x + src_row))[tid];

    float sum = v.x + v.y + v.z + v.w;
    #pragma unroll
    for (int o = 16; o > 0; o >>= 1) sum += __shfl_xor_sync(0xffffffffu, sum, o);
    if ((tid & 31) == 0) sh[tid >> 5] = sum;
    __syncthreads();
    float mean = (sh[0] + sh[1] + sh[2] + sh[3]) * (1.0f / CC);
    __syncthreads();

    float d0 = v.x - mean, d1 = v.y - mean, d2 = v.z - mean, d3 = v.w - mean;
    float sq = d0*d0 + d1*d1 + d2*d2 + d3*d3;
    #pragma unroll
    for (int o = 16; o > 0; o >>= 1) sq += __shfl_xor_sync(0xffffffffu, sq, o);
    if ((tid & 31) == 0) sh[tid >> 5] = sq;
    __syncthreads();
    float var = (sh[0] + sh[1] + sh[2] + sh[3]) * (1.0f / CC);
    float inv = rsqrtf(var + EPSF);

    float4 w4 = ((const float4*)w)[tid];
    float4 b4 = ((const float4*)b)[tid];
    __half2 h01 = __floats2half2_rn(d0 * inv * w4.x + b4.x, d1 * inv * w4.y + b4.y);
    __half2 h23 = __floats2half2_rn(d2 * inv * w4.z + b4.z, d3 * inv * w4.w + b4.w);
    uint2 pk = { *(uint32_t*)&h01, *(uint32_t*)&h23 };
    *(uint2*)(out + dst_row + tid * 4) = pk;
}

// ---------------- fp16 HMMA GEMM: C[M,N] = A[M,K] @ Bw[N,K]^T --------------
#define EPI_PLAIN       0
#define EPI_GELU        1
#define EPI_SCATTER_RES 2
#define EPI_RES         3

#define HSTAGE    20480
#define HSM_TOTAL 61440

__device__ __forceinline__ void cp_stage(uint32_t da, uint32_t db,
                                         const __half* pa, const __half* pb) {
    #pragma unroll
    for (int j = 0; j < 4; j++) {
        CP16(da + j * 16, pa + j * 8);
        CP16(db + j * 16, pb + j * 8);
    }
    CP_COMMIT();
}

template<int EPI>
__global__ __launch_bounds__(128, 2)
void h_gemm(const __half* __restrict__ A,
            const __half* __restrict__ Bw,
            const float* __restrict__ bias,
            float* __restrict__ outf,
            __half* __restrict__ outh,
            int Nc, int K,
            const float* __restrict__ Res)
{
    extern __shared__ char smem[];

    const int tid  = threadIdx.x;     // 128
    const int lane = tid & 31;
    const int w    = tid >> 5;        // 4 warps
    const int wr   = (w >> 1) * 64;
    const int wc   = (w & 1)  * 64;
    const int bm   = blockIdx.y * 128;
    const int bn   = blockIdx.x * 128;

    const uint32_t sb = s2u(smem);

    const __half* gA = A  + (size_t)(bm + tid) * K;
    const __half* gB = Bw + (size_t)(bn + tid) * K;
    const uint32_t rowA = sb + tid * 80;
    const uint32_t rowB = sb + 10240 + tid * 80;

    float acc[4][8][4];
    #pragma unroll
    for (int i = 0; i < 4; i++)
        #pragma unroll
        for (int j = 0; j < 8; j++)
            #pragma unroll
            for (int q = 0; q < 4; q++) acc[i][j][q] = 0.f;

    const int nch = K >> 5;

    const int tile = lane >> 3, rit = lane & 7;
    uint32_t aOff[4], bOff[4];
    #pragma unroll
    for (int mb = 0; mb < 4; mb++)
        aOff[mb] = (uint32_t)((wr + mb * 16 + (tile & 1) * 8 + rit) * 80 + (tile >> 1) * 16);
    #pragma unroll
    for (int p = 0; p < 4; p++)
        bOff[p] = (uint32_t)(10240 + (wc + p * 16 + (tile >> 1) * 8 + rit) * 80 + (tile & 1) * 16);

    cp_stage(rowA, rowB, gA, gB);
    cp_stage(rowA + HSTAGE, rowB + HSTAGE, gA + 32, gB + 32);

    int st_ld = 2;
    for (int c = 0; c < nch; c++) {
        CP_WAIT(1);
        __syncthreads();
        if (c + 2 < nch) {
            cp_stage(rowA + st_ld * HSTAGE, rowB + st_ld * HSTAGE,
                     gA + (c + 2) * 32, gB + (c + 2) * 32);
        }
        const uint32_t stb = sb + (uint32_t)((c == 0) ? 0 : (c % 3)) * HSTAGE;
        #pragma unroll
        for (int kk = 0; kk < 2; kk++) {
            uint32_t a[4][4], b[4][4];
            #pragma unroll
            for (int mb = 0; mb < 4; mb++) LDSM4(a[mb], stb + aOff[mb] + kk * 32);
            #pragma unroll
            for (int p = 0; p < 4; p++)    LDSM4(b[p],  stb + bOff[p] + kk * 32);
            #pragma unroll
            for (int mb = 0; mb < 4; mb++)
                #pragma unroll
                for (int nb = 0; nb < 8; nb++)
                    mma_f16(acc[mb][nb], a[mb], &b[nb >> 1][(nb & 1) * 2]);
        }
        st_ld = (st_ld == 2) ? 0 : st_ld + 1;
    }

    const int fr = lane >> 2, fc = lane & 3;
    #pragma unroll
    for (int mb = 0; mb < 4; mb++) {
        const int m0 = bm + wr + mb * 16 + fr;
        const int m1 = m0 + 8;
        size_t ob0, ob1;
        if (EPI == EPI_SCATTER_RES) { ob0 = scatter_base(m0); ob1 = scatter_base(m1); }
        else                        { ob0 = (size_t)m0 * Nc;  ob1 = (size_t)m1 * Nc; }
        #pragma unroll
        for (int nb = 0; nb < 8; nb++) {
            const int n0 = bn + wc + nb * 8 + 2 * fc;
            float2 bb = *(const float2*)(bias + n0);
            float v0 = acc[mb][nb][0] + bb.x;
            float v1 = acc[mb][nb][1] + bb.y;
            float v2 = acc[mb][nb][2] + bb.x;
            float v3 = acc[mb][nb][3] + bb.y;
            if (EPI == EPI_GELU) {
                v0 = 0.5f * v0 * (1.0f + erff(v0 * 0.70710678118654752f));
                v1 = 0.5f * v1 * (1.0f + erff(v1 * 0.70710678118654752f));
                v2 = 0.5f * v2 * (1.0f + erff(v2 * 0.70710678118654752f));
                v3 = 0.5f * v3 * (1.0f + erff(v3 * 0.70710678118654752f));
            } else if (EPI == EPI_SCATTER_RES || EPI == EPI_RES) {
                float2 r0 = *(const float2*)(Res + ob0 + n0);
                float2 r1 = *(const float2*)(Res + ob1 + n0);
                v0 += r0.x; v1 += r0.y; v2 += r1.x; v3 += r1.y;
            }
            if (EPI == EPI_PLAIN || EPI == EPI_GELU) {
                *(uint32_t*)(outh + ob0 + n0) = pkh2(v0, v1);
                *(uint32_t*)(outh + ob1 + n0) = pkh2(v2, v3);
            } else {
                *(float2*)(outf + ob0 + n0) = make_float2(v0, v1);
                *(float2*)(outf + ob1 + n0) = make_float2(v2, v3);
            }
        }
    }
}

// ---------------- HMMA windowed attention ----------------------------------
// block = (head, bw), 128 threads / 4 warps; warp w owns window rows 16w..16w+15
#define BMS 68   // sBM float stride

__global__ __launch_bounds__(128)
void attn_mma(const __half* __restrict__ qkv,
              const float* __restrict__ bm,
              __half* __restrict__ outp)
{
    int head = blockIdx.x;
    int bw   = blockIdx.y;
    int wim  = bw & 63;
    int tid  = threadIdx.x;
    int lane = tid & 31;
    int w    = tid >> 5;
    int wr   = w * 16;

    __shared__ __half sQ[64*40], sK[64*40], sV[64*40];
    __shared__ float  sBM[64*BMS];

    // load Q/K/V (64 rows x 32 halves each)
    size_t rowbase = (size_t)(bw * 64) * 1536 + head * 32;
    for (int i = tid; i < 256; i += 128) {
        int n = i >> 2, c = i & 3;
        const __half* src = qkv + rowbase + (size_t)n * 1536 + c * 8;
        *(uint4*)(sQ + n * 40 + c * 8) = *(const uint4*)src;
        *(uint4*)(sK + n * 40 + c * 8) = *(const uint4*)(src + 512);
        *(uint4*)(sV + n * 40 + c * 8) = *(const uint4*)(src + 1024);
    }
    // load bias+mask (64x64 f32)
    {
        const float4* src = (const float4*)(bm + ((size_t)head * 64 + wim) * 4096);
        for (int e = tid; e < 1024; e += 128) {
            int n = e >> 4, c = e & 15;
            *(float4*)(sBM + n * BMS + c * 4) = src[e];
        }
    }
    __syncthreads();

    const uint32_t uQ = s2u(sQ), uK = s2u(sK), uV = s2u(sV);
    const int tile = lane >> 3, rit = lane & 7;
    const int fr = lane >> 2, fc = lane & 3;

    // Q A-fragments (rows wr..wr+15, k=0..31)
    uint32_t aQ[2][4];
    #pragma unroll
    for (int kt = 0; kt < 2; kt++)
        LDSM4(aQ[kt], uQ + (uint32_t)(((wr + (tile & 1) * 8 + rit) * 40
                                       + (tile >> 1) * 8 + kt * 16) * 2));

    // K B-fragments (n = tokens, 4 pair-tiles x 2 k-tiles)
    uint32_t bK[4][2][4];
    #pragma unroll
    for (int pt = 0; pt < 4; pt++)
        #pragma unroll
        for (int kt = 0; kt < 2; kt++)
            LDSM4(bK[pt][kt], uK + (uint32_t)(((pt * 16 + (tile >> 1) * 8 + rit) * 40
                                               + (tile & 1) * 8 + kt * 16) * 2));

    // S = Q K^T   (16 x 64 per warp)
    float c[8][4];
    #pragma unroll
    for (int i = 0; i < 8; i++)
        #pragma unroll
        for (int j = 0; j < 4; j++) c[i][j] = 0.f;
    #pragma unroll
    for (int pt = 0; pt < 4; pt++)
        #pragma unroll
        for (int kt = 0; kt < 2; kt++) {
            mma_f16(c[2 * pt],     aQ[kt], &bK[pt][kt][0]);
            mma_f16(c[2 * pt + 1], aQ[kt], &bK[pt][kt][2]);
        }

    // scale + bias/mask + softmax (rows fr, fr+8 of warp strip)
    const float* bm0 = sBM + (wr + fr) * BMS;
    const float* bm1 = bm0 + 8 * BMS;
    float mx0 = -1e30f, mx1 = -1e30f;
    #pragma unroll
    for (int nt = 0; nt < 8; nt++) {
        float2 b0 = *(const float2*)(bm0 + nt * 8 + 2 * fc);
        float2 b1 = *(const float2*)(bm1 + nt * 8 + 2 * fc);
        c[nt][0] = c[nt][0] * SCALE_F + b0.x;
        c[nt][1] = c[nt][1] * SCALE_F + b0.y;
        c[nt][2] = c[nt][2] * SCALE_F + b1.x;
        c[nt][3] = c[nt][3] * SCALE_F + b1.y;
        mx0 = fmaxf(mx0, fmaxf(c[nt][0], c[nt][1]));
        mx1 = fmaxf(mx1, fmaxf(c[nt][2], c[nt][3]));
    }
    mx0 = fmaxf(mx0, __shfl_xor_sync(0xffffffffu, mx0, 1));
    mx0 = fmaxf(mx0, __shfl_xor_sync(0xffffffffu, mx0, 2));
    mx1 = fmaxf(mx1, __shfl_xor_sync(0xffffffffu, mx1, 1));
    mx1 = fmaxf(mx1, __shfl_xor_sync(0xffffffffu, mx1, 2));

    float s0 = 0.f, s1 = 0.f;
    #pragma unroll
    for (int nt = 0; nt < 8; nt++) {
        c[nt][0] = __expf(c[nt][0] - mx0);
        c[nt][1] = __expf(c[nt][1] - mx0);
        c[nt][2] = __expf(c[nt][2] - mx1);
        c[nt][3] = __expf(c[nt][3] - mx1);
        s0 += c[nt][0] + c[nt][1];
        s1 += c[nt][2] + c[nt][3];
    }
    s0 += __shfl_xor_sync(0xffffffffu, s0, 1);
    s0 += __shfl_xor_sync(0xffffffffu, s0, 2);
    s1 += __shfl_xor_sync(0xffffffffu, s1, 1);
    s1 += __shfl_xor_sync(0xffffffffu, s1, 2);
    float i0 = 1.0f / s0, i1 = 1.0f / s1;

    // pack P (fp16) directly into A-fragments
    uint32_t aP[4][4];
    #pragma unroll
    for (int kt = 0; kt < 4; kt++) {
        aP[kt][0] = pkh2(c[2*kt][0] * i0,   c[2*kt][1] * i0);
        aP[kt][1] = pkh2(c[2*kt][2] * i1,   c[2*kt][3] * i1);
        aP[kt][2] = pkh2(c[2*kt+1][0] * i0, c[2*kt+1][1] * i0);
        aP[kt][3] = pkh2(c[2*kt+1][2] * i1, c[2*kt+1][3] * i1);
    }

    // O = P V   (V B-frags via ldmatrix.trans)
    float o[4][4];
    #pragma unroll
    for (int i = 0; i < 4; i++)
        #pragma unroll
        for (int j = 0; j < 4; j++) o[i][j] = 0.f;
    #pragma unroll
    for (int kt = 0; kt < 4; kt++)
        #pragma unroll
        for (int dh = 0; dh < 2; dh++) {
            uint32_t bV[4];
            LDSM4T(bV, uV + (uint32_t)(((kt * 16 + ((lane >> 3) & 1) * 8 + (lane & 7)) * 40
                                        + (lane >> 4) * 8 + dh * 16) * 2));
            mma_f16(o[2 * dh],     aP[kt], &bV[0]);
            mma_f16(o[2 * dh + 1], aP[kt], &bV[2]);
        }

    // store O (fp16)
    size_t orow = (size_t)(bw * 64 + wr + fr) * 512 + head * 32;
    #pragma unroll
    for (int nt = 0; nt < 4; nt++) {
        *(uint32_t*)(outp + orow + nt * 8 + 2 * fc)             = pkh2(o[nt][0], o[nt][1]);
        *(uint32_t*)(outp + orow + 8 * 512 + nt * 8 + 2 * fc)   = pkh2(o[nt][2], o[nt][3]);
    }
}

// ---------------- launch ----------------
extern "C" void kernel_launch(void* const* d_in, const int* in_sizes, int n_in,
                              void* d_out, int out_size)
{
    const float* x      = (const float*)d_in[0];
    const float* qkv_w  = (const float*)d_in[1];
    const float* qkv_b  = (const float*)d_in[2];
    const float* proj_w = (const float*)d_in[3];
    const float* proj_b = (const float*)d_in[4];
    const float* n1w    = (const float*)d_in[5];
    const float* n1b    = (const float*)d_in[6];
    const float* n2w    = (const float*)d_in[7];
    const float* n2b    = (const float*)d_in[8];
    const float* fc1w   = (const float*)d_in[9];
    const float* fc1b   = (const float*)d_in[10];
    const float* fc2w   = (const float*)d_in[11];
    const float* fc2b   = (const float*)d_in[12];
    const float* rbt    = (const float*)d_in[13];
    const int*   rpi    = (const int*)d_in[14];
    const float* amask  = (const float*)d_in[15];
    float*       out    = (float*)d_out;

    __half *hwin, *qkvb, *ob, *h2nb, *hidb, *wq, *wp, *w1, *w2;
    float *x1b, *bmb;
    cudaGetSymbolAddress((void**)&hwin, g_hwin);
    cudaGetSymbolAddress((void**)&qkvb, g_qkv);
    cudaGetSymbolAddress((void**)&ob,   g_o);
    cudaGetSymbolAddress((void**)&x1b,  g_x1);
    cudaGetSymbolAddress((void**)&h2nb, g_h2n);
    cudaGetSymbolAddress((void**)&hidb, g_hid);
    cudaGetSymbolAddress((void**)&wq,   g_wq);
    cudaGetSymbolAddress((void**)&wp,   g_wp);
    cudaGetSymbolAddress((void**)&w1,   g_w1);
    cudaGetSymbolAddress((void**)&w2,   g_w2);
    cudaGetSymbolAddress((void**)&bmb,  g_bm);

    cudaFuncSetAttribute(h_gemm<EPI_PLAIN>,       cudaFuncAttributeMaxDynamicSharedMemorySize, HSM_TOTAL);
    cudaFuncSetAttribute(h_gemm<EPI_GELU>,        cudaFuncAttributeMaxDynamicSharedMemorySize, HSM_TOTAL);
    cudaFuncSetAttribute(h_gemm<EPI_SCATTER_RES>, cudaFuncAttributeMaxDynamicSharedMemorySize, HSM_TOTAL);
    cudaFuncSetAttribute(h_gemm<EPI_RES>,         cudaFuncAttributeMaxDynamicSharedMemorySize, HSM_TOTAL);

    // 0) convert weights; precompute bias+mask table
    cvtw<<<(3*CC*CC/4 + 255)/256, 256>>>(qkv_w,  wq, 3*CC*CC/4);
    cvtw<<<(CC*CC/4   + 255)/256, 256>>>(proj_w, wp, CC*CC/4);
    cvtw<<<(HID*CC/4  + 255)/256, 256>>>(fc1w,   w1, HID*CC/4);
    cvtw<<<(CC*HID/4  + 255)/256, 256>>>(fc2w,   w2, CC*HID/4);
    bmprep<<<1024, 256>>>(amask, rbt, rpi, bmb);

    // 1) LN1 + shift + window partition -> fp16
    ln_kernel<true><<<MTOK, 128>>>(x, n1w, n1b, hwin);

    // 2) QKV GEMM
    h_gemm<EPI_PLAIN><<<dim3(1536/128, MTOK/128), 128, HSM_TOTAL>>>(
        hwin, wq, qkv_b, nullptr, qkvb, 1536, 512, nullptr);

    // 3) HMMA windowed attention
    attn_mma<<<dim3(HEADS, BB*64), 128>>>(qkvb, bmb, ob);

    // 4) proj GEMM + window reverse + roll + residual -> x1 (fp32)
    h_gemm<EPI_SCATTER_RES><<<dim3(512/128, MTOK/128), 128, HSM_TOTAL>>>(
        ob, wp, proj_b, x1b, nullptr, 512, 512, x);

    // 5) LN2 -> fp16
    ln_kernel<false><<<MTOK, 128>>>(x1b, n2w, n2b, h2nb);

    // 6) FC1 + GELU -> fp16
    h_gemm<EPI_GELU><<<dim3(2048/128, MTOK/128), 128, HSM_TOTAL>>>(
        h2nb, w1, fc1b, nullptr, hidb, 2048, 512, nullptr);

    // 7) FC2 + residual -> out (fp32)
    h_gemm<EPI_RES><<<dim3(512/128, MTOK/128), 128, HSM_TOTAL>>>(
        hidb, w2, fc2b, out, nullptr, 512, 2048, x1b);
}